// round 3
// baseline (speedup 1.0000x reference)
#include <cuda_runtime.h>
#include <math.h>

// Problem constants (fixed by setup_inputs)
#define BB   32
#define AA   3
#define HH   64
#define WW   64
#define CC   80
#define PRED_LAST 85
#define NT   2048
#define CELLS (BB*AA*HH*WW)   // 393216

#define THREADS_A 128
#define BLOCKS_A  512          // 512*4 warps = 2048 = NT; 512*128 = 65536 threads
#define CPT       6            // 65536 * 6 = 393216 cells
#define NTHREADS_TOT (BLOCKS_A*THREADS_A)

// Zero-initialized device scratch. kernel B resets every touched mask cell;
// all other arrays are fully overwritten each call => replay-deterministic.
__device__ int    g_mask[CELLS];        // bit0=obj, bit1=kz, bit2=cross-applied
__device__ int    g_list[NT*4];         // claimed cells (or -1), 4 slots/target
__device__ double g_pconf[BLOCKS_A];
__device__ double g_pcls [BLOCKS_A];
__device__ double g_pxywh[BLOCKS_A];
__device__ int    g_pcnt [BLOCKS_A];    // (n_obj<<20)|(n_kz<<10)|n_cross

__device__ __forceinline__ float softplusf(float x) {
    return fmaxf(x, 0.0f) + log1pf(expf(-fabsf(x)));
}
__device__ __forceinline__ float wsumf(float v) {
    #pragma unroll
    for (int o = 16; o > 0; o >>= 1) v += __shfl_down_sync(0xFFFFFFFFu, v, o);
    return v;
}
__device__ __forceinline__ int wsumi(int v) {
    #pragma unroll
    for (int o = 16; o > 0; o >>= 1) v += __shfl_down_sync(0xFFFFFFFFu, v, o);
    return v;
}

// ---------------------------------------------------------------------------
// Kernel A: everything except the final reduction.
//   - every thread streams 6 conf-base cells (MLP=6 gathers)
//   - every warp additionally owns one target: IoU argmax, mask claims with
//     order-independent conf corrections, xywh MSE, 80-ch cls BCE
// ---------------------------------------------------------------------------
__global__ void __launch_bounds__(THREADS_A) k_main(const float* __restrict__ pred,
                                                    const float* __restrict__ target,
                                                    const float* __restrict__ anchors)
{
    const int tid  = threadIdx.x;
    const int lane = tid & 31;
    const int wrp  = tid >> 5;
    const int tgid = blockIdx.x * THREADS_A + tid;   // 0..65535
    const int wgid = blockIdx.x * 4 + wrp;           // 0..2047 == target id

    // ---- conf base stream (batched loads, independent of everything) ----
    float pcv[CPT];
    #pragma unroll
    for (int k = 0; k < CPT; ++k)
        pcv[k] = __ldg(pred + (tgid + k * NTHREADS_TOT) * PRED_LAST + 4);

    // ---- target work ----
    const float* t = target + wgid * 6;
    const float tb = __ldg(t + 0);
    const float tl = __ldg(t + 1);
    const float tx = __ldg(t + 2) * (float)HH;
    const float ty = __ldg(t + 3) * (float)HH;
    const float tw = __ldg(t + 4) * (float)HH;
    const float th = __ldg(t + 5) * (float)HH;
    const int b   = (int)tb;
    const int lab = (int)tl;
    const int wi  = (int)tw;
    const int hi  = (int)th;

    float ious[AA];
    float best = -1.0f;
    int   besta = 0;
    #pragma unroll
    for (int a = 0; a < AA; ++a) {
        const float aw = __ldg(anchors + 2*a), ah = __ldg(anchors + 2*a + 1);
        const float inter = fminf(aw, tw) * fminf(ah, th);
        const float iou = inter / (aw*ah + tw*th - inter);
        ious[a] = iou;
        if (iou > best) { best = iou; besta = a; }
    }
    const int cell_best = ((b*AA + besta)*HH + hi)*WW + wi;
    const float* prow = pred + cell_best * PRED_LAST;

    // conf base partial
    float conf = 0.0f;
    #pragma unroll
    for (int k = 0; k < CPT; ++k) conf += softplusf(pcv[k]);

    // ---- claims + corrections (lanes 0-2: kz per anchor, lane 3: obj+xywh)
    float xywh = 0.0f;
    int n_obj = 0, n_kz = 0, n_cross = 0;
    int list_val = -1;

    if (lane < 3) {
        if (ious[lane] > 0.5f) {
            const int c = ((b*AA + lane)*HH + hi)*WW + wi;
            const float pc = __ldg(pred + c * PRED_LAST + 4);
            const int old = atomicOr(&g_mask[c], 2);
            if (!(old & 2)) {
                conf -= softplusf(pc);
                n_kz = 1; list_val = c;
                if (old & 1) {      // I'm the later of the (obj,kz) pair
                    const int o2 = atomicOr(&g_mask[c], 4);
                    if (!(o2 & 4)) { conf += softplusf(pc); n_cross = 1; }
                }
            }
        }
    } else if (lane == 3) {
        const int c = cell_best;
        const float pc = __ldg(prow + 4);
        const int old = atomicOr(&g_mask[c], 1);
        if (!(old & 1)) {
            conf -= pc;
            n_obj = 1; list_val = c;
            if (old & 2) {
                const int o2 = atomicOr(&g_mask[c], 4);
                if (!(o2 & 4)) { conf += softplusf(pc); n_cross = 1; }
            }
        }
        // xywh MSE
        const float fx = tx - floorf(tx);
        const float fy = ty - floorf(ty);
        const float lw = logf(tw / __ldg(anchors + 2*besta));
        const float lh = logf(th / __ldg(anchors + 2*besta + 1));
        const float d0 = prow[0] - fx, d1 = prow[1] - fy;
        const float d2 = prow[2] - lw, d3 = prow[3] - lh;
        xywh = d0*d0 + d1*d1 + d2*d2 + d3*d3;
    }
    if (lane < 4) g_list[wgid*4 + lane] = list_val;   // all slots written each call

    // ---- cls BCE over one-hot (80 channels across the warp) ----
    const float* pcls = prow + 5;
    const float x0 = __ldg(pcls + lane);
    const float x1 = __ldg(pcls + lane + 32);
    const float x2 = (lane < 16) ? __ldg(pcls + lane + 64) : 0.0f;
    float cls = softplusf(x0) + softplusf(x1);
    if (lane < 16) cls += softplusf(x2);
    if (lab < 32) { if (lane == lab)      cls -= x0; }
    else if (lab < 64) { if (lane == lab - 32) cls -= x1; }
    else { if (lane == lab - 64) cls -= x2; }

    // ---- block reduction -> per-block partials (no global atomics) ----
    conf = wsumf(conf);
    cls  = wsumf(cls);
    xywh = wsumf(xywh);
    int cnt = wsumi((n_obj << 20) | (n_kz << 10) | n_cross);

    __shared__ float sc[4], sl[4], sx[4];
    __shared__ int   si[4];
    if (lane == 0) { sc[wrp] = conf; sl[wrp] = cls; sx[wrp] = xywh; si[wrp] = cnt; }
    __syncthreads();
    if (tid == 0) {
        double dc = 0.0, dl = 0.0, dx = 0.0; int ci = 0;
        #pragma unroll
        for (int w = 0; w < 4; ++w) { dc += (double)sc[w]; dl += (double)sl[w]; dx += (double)sx[w]; ci += si[w]; }
        g_pconf[blockIdx.x] = dc;
        g_pcls [blockIdx.x] = dl;
        g_pxywh[blockIdx.x] = dx;
        g_pcnt [blockIdx.x] = ci;
    }
}

// ---------------------------------------------------------------------------
// Kernel B: reset masks from the list, reduce 512 partials, write the loss.
// ---------------------------------------------------------------------------
__global__ void __launch_bounds__(512) k_final(float* __restrict__ out)
{
    const int tid = threadIdx.x;

    // reset touched mask cells (list fully rewritten by kernel A each call)
    #pragma unroll
    for (int i = tid; i < NT*4; i += 512) {
        const int c = g_list[i];
        if (c >= 0) g_mask[c] = 0;
    }

    double dc = g_pconf[tid];
    double dl = g_pcls [tid];
    double dx = g_pxywh[tid];
    long long ci = (long long)g_pcnt[tid];

    // warp reduce
    #pragma unroll
    for (int o = 16; o > 0; o >>= 1) {
        dc += __shfl_down_sync(0xFFFFFFFFu, dc, o);
        dl += __shfl_down_sync(0xFFFFFFFFu, dl, o);
        dx += __shfl_down_sync(0xFFFFFFFFu, dx, o);
        ci += __shfl_down_sync(0xFFFFFFFFu, ci, o);
    }
    __shared__ double wc[16], wl[16], wx[16];
    __shared__ long long wi_[16];
    const int lane = tid & 31, wrp = tid >> 5;
    if (lane == 0) { wc[wrp] = dc; wl[wrp] = dl; wx[wrp] = dx; wi_[wrp] = ci; }
    __syncthreads();

    if (tid == 0) {
        double c = 0.0, l = 0.0, x = 0.0; long long n = 0;
        #pragma unroll
        for (int w = 0; w < 16; ++w) { c += wc[w]; l += wl[w]; x += wx[w]; n += wi_[w]; }
        const long long nobj   = (n >> 20) & 0xFFFFF;
        const long long nkz    = (n >> 10) & 0x3FF;
        const long long ncross =  n        & 0x3FF;
        const double n_noobj = (double)CELLS - (double)nobj - (double)nkz + (double)ncross;
        const double loss = x / ((double)NT * 4.0)
                          + c / ((double)nobj + n_noobj)
                          + l / ((double)NT * (double)CC);
        out[0] = (float)loss;
    }
}

extern "C" void kernel_launch(void* const* d_in, const int* in_sizes, int n_in,
                              void* d_out, int out_size)
{
    const float* pred    = (const float*)d_in[0];
    const float* target  = (const float*)d_in[1];
    const float* anchors = (const float*)d_in[2];
    float* out = (float*)d_out;

    k_main<<<BLOCKS_A, THREADS_A>>>(pred, target, anchors);
    k_final<<<1, 512>>>(out);
}